// round 16
// baseline (speedup 1.0000x reference)
#include <cuda_runtime.h>

#define TT 64
#define BB 1024
#define II 64
#define HH 256

__device__ float g_hs[(size_t)TT * BB * HH];
__device__ float g_WT[HH * HH];   // WT[k][h] = W_hh[h][k]

typedef unsigned long long u64;

#define FMA_F32X2(d, a, b, c) \
    asm("fma.rn.f32x2 %0, %1, %2, %3;" : "=l"(d) : "l"(a), "l"(b), "l"(c))
#define PACK_F32X2(out, lo, hi) \
    asm("mov.b64 %0, {%1, %2};" : "=l"(out) : "f"(lo), "f"(hi))
#define UNPACK_F32X2(lo, hi, in) \
    asm("mov.b64 {%0, %1}, %2;" : "=f"(lo), "=f"(hi) : "l"(in))

// ---------------------------------------------------------------------------
// Kernel 0: transpose W_hh (one-time, 256 KB)
// ---------------------------------------------------------------------------
__global__ void __launch_bounds__(256) wt_kernel(const float* __restrict__ W_hh)
{
    const int k = blockIdx.x;
    const int h = threadIdx.x;
    g_WT[k * HH + h] = W_hh[h * HH + k];
}

// ---------------------------------------------------------------------------
// Kernel 1: g_hs[t,b,h] = data[t,b,:] . W_ih[h,:] + b_ih[h] + b_hh[h]
// 16-row tiles -> 4 barrier-pairs (was 16).
// ---------------------------------------------------------------------------
__global__ void __launch_bounds__(256) xw_kernel(
    const float* __restrict__ data,
    const float* __restrict__ W_ih,
    const float* __restrict__ b_ih,
    const float* __restrict__ b_hh)
{
    __shared__ float sX[1024];   // 16 rows x 64 inputs
    const int tid = threadIdx.x;
    const long r0 = (long)blockIdx.x * 64;

    float w[64];
    const float4* W4 = reinterpret_cast<const float4*>(W_ih) + tid * 16;
#pragma unroll
    for (int c = 0; c < 16; c++) {
        float4 v = W4[c];
        w[4*c+0] = v.x; w[4*c+1] = v.y; w[4*c+2] = v.z; w[4*c+3] = v.w;
    }
    const float bsum = b_ih[tid] + b_hh[tid];
    const float4* D4 = reinterpret_cast<const float4*>(data + r0 * II);

    for (int it = 0; it < 4; it++) {
        __syncthreads();
        reinterpret_cast<float4*>(sX)[tid] = D4[it * 256 + tid];
        __syncthreads();

        const float4* X4 = reinterpret_cast<const float4*>(sX);
#pragma unroll
        for (int r = 0; r < 16; r++) {
            float a = bsum;
#pragma unroll
            for (int c = 0; c < 16; c++) {
                float4 x = X4[r * 16 + c];
                a += x.x*w[4*c] + x.y*w[4*c+1] + x.z*w[4*c+2] + x.w*w[4*c+3];
            }
            g_hs[(r0 + it * 16 + r) * HH + tid] = a;
        }
    }
}

// ---------------------------------------------------------------------------
// Kernel 2: persistent RNN scan, k-split (validated).
// ---------------------------------------------------------------------------
__global__ void __launch_bounds__(512) rnn_scan_kernel(
    const float* __restrict__ h0_in)
{
    extern __shared__ float sm[];
    float* hp   = sm;                 // [2][8][260]
    float* part = sm + 2 * 8 * 260;   // [8][2048]

    const int tid = threadIdx.x;
    const int kq = tid >> 6;
    const int hw = tid & 63;
    const int b0 = blockIdx.x * 8;

    for (int m = tid; m < 2048; m += 512) {
        int bb = m >> 8, k = m & 255;
        hp[bb * 260 + k] = h0_in[(size_t)(b0 + bb) * HH + k];
    }
    __syncthreads();

    const int off = tid * 4;
    const int rb_b = off >> 8;
    const int rb_h = off & 255;

    for (int t = 0; t < TT; t++) {
        const int rb = t & 1;
        const float* hpc = hp + rb * 8 * 260;

        u64 acc[8][2];
#pragma unroll
        for (int bb = 0; bb < 8; bb++) { acc[bb][0] = 0ULL; acc[bb][1] = 0ULL; }

#pragma unroll 2
        for (int k4 = 0; k4 < 8; k4++) {
            const int k = kq * 32 + k4 * 4;
            const ulonglong2* wr =
                reinterpret_cast<const ulonglong2*>(g_WT + (size_t)k * HH) + hw;
            ulonglong2 w0 = wr[0];
            ulonglong2 w1 = wr[64];
            ulonglong2 w2 = wr[128];
            ulonglong2 w3 = wr[192];
#pragma unroll
            for (int bb = 0; bb < 8; bb++) {
                float4 hv = *reinterpret_cast<const float4*>(hpc + bb * 260 + k);
                u64 hd;
                PACK_F32X2(hd, hv.x, hv.x);
                FMA_F32X2(acc[bb][0], w0.x, hd, acc[bb][0]);
                FMA_F32X2(acc[bb][1], w0.y, hd, acc[bb][1]);
                PACK_F32X2(hd, hv.y, hv.y);
                FMA_F32X2(acc[bb][0], w1.x, hd, acc[bb][0]);
                FMA_F32X2(acc[bb][1], w1.y, hd, acc[bb][1]);
                PACK_F32X2(hd, hv.z, hv.z);
                FMA_F32X2(acc[bb][0], w2.x, hd, acc[bb][0]);
                FMA_F32X2(acc[bb][1], w2.y, hd, acc[bb][1]);
                PACK_F32X2(hd, hv.w, hv.w);
                FMA_F32X2(acc[bb][0], w3.x, hd, acc[bb][0]);
                FMA_F32X2(acc[bb][1], w3.y, hd, acc[bb][1]);
            }
        }

#pragma unroll
        for (int bb = 0; bb < 8; bb++) {
            float f0, f1, f2, f3;
            UNPACK_F32X2(f0, f1, acc[bb][0]);
            UNPACK_F32X2(f2, f3, acc[bb][1]);
            *reinterpret_cast<float4*>(part + kq * 2048 + bb * 256 + hw * 4) =
                make_float4(f0, f1, f2, f3);
        }
        __syncthreads();

        {
            float* hs_t = g_hs + (size_t)t * BB * HH;
            float4 r = *reinterpret_cast<const float4*>(
                hs_t + (size_t)(b0 + rb_b) * HH + rb_h);
#pragma unroll
            for (int q = 0; q < 8; q++) {
                float4 pv = *reinterpret_cast<const float4*>(part + q * 2048 + off);
                r.x += pv.x; r.y += pv.y; r.z += pv.z; r.w += pv.w;
            }
            r.x = fmaxf(r.x, 0.f); r.y = fmaxf(r.y, 0.f);
            r.z = fmaxf(r.z, 0.f); r.w = fmaxf(r.w, 0.f);
            *reinterpret_cast<float4*>(
                hs_t + (size_t)(b0 + rb_b) * HH + rb_h) = r;
            *reinterpret_cast<float4*>(
                hp + (rb ^ 1) * 8 * 260 + rb_b * 260 + rb_h) = r;
        }
        __syncthreads();
    }
}

// ---------------------------------------------------------------------------
// Kernel 3: attention. ONE block per b (512 thr, 64 i), SINGLE h-contiguous
// gather layout (Gsh). Scores now read with the SAME conflict-free chunk
// pattern as context (lane owns h = 4hq+64c+e): 9n x 4 LDS.128, natural
// h-pair u64 operands, zero packs. hs cached once as u64 chunk pairs and
// reused by scores AND head. Stagers store only Gsh (9 conflict-free STS).
// Split-reduce butterfly + single barrier per j retained.
// ---------------------------------------------------------------------------
#define GSH_STRIDE 264       // 256 h + 8 pad (words)

__global__ void __launch_bounds__(512, 1) attn_kernel(
    const int* __restrict__ nine_idx,
    const float* __restrict__ W_lin,
    const float* __restrict__ b_lin,
    float* __restrict__ out)
{
    __shared__ float Gsh[2][9 * GSH_STRIDE];
    __shared__ float sWl[512];
    __shared__ int   sidx[9];

    const int tid   = threadIdx.x;
    const int b     = blockIdx.x;
    const int iq    = tid >> 4;          // 0..31
    const int hq    = tid & 15;          // 0..15
    const int iA    = 2 * iq;
    const int iB    = iA + 1;
    const bool isB  = (tid & 8) != 0;    // bit3 of the 16-lane reduce group
    const bool stager = (tid < 256);     // threads that stage the gather tile

    if (tid < 9) sidx[tid] = nine_idx[b * 9 + tid];
    sWl[tid] = W_lin[tid];
    __syncthreads();

    int idxr[9];
#pragma unroll
    for (int n = 0; n < 9; n++) idxr[n] = sidx[n];

    // hs rows cached as u64 h-pairs over the chunk pattern (4hq + 64c + e)
    u64 hspA[8], hspB[8];
    {
        const float* HA = g_hs + ((size_t)iA * BB + b) * HH + 4 * hq;
        const float* HB = g_hs + ((size_t)iB * BB + b) * HH + 4 * hq;
#pragma unroll
        for (int c = 0; c < 4; c++) {
            ulonglong2 va = *reinterpret_cast<const ulonglong2*>(HA + 64 * c);
            ulonglong2 vb = *reinterpret_cast<const ulonglong2*>(HB + 64 * c);
            hspA[2*c] = va.x; hspA[2*c+1] = va.y;
            hspB[2*c] = vb.x; hspB[2*c+1] = vb.y;
        }
    }

    u64 acc2[2][4][2];
#pragma unroll
    for (int i = 0; i < 2; i++)
#pragma unroll
        for (int c = 0; c < 4; c++) { acc2[i][c][0] = 0ULL; acc2[i][c][1] = 0ULL; }

    const float bl = b_lin[0];

    // stagers prefetch gather rows for j = 0 (row h = tid)
    float gr[9];
    if (stager) {
#pragma unroll
        for (int n = 0; n < 9; n++) {
            int iv = idxr[n];
            gr[n] = (iv < BB) ? g_hs[(size_t)iv * HH + tid] : 0.f;
        }
    }

    float* out_attn = out + (size_t)TT * BB;

    for (int j = 0; j < TT; j++) {
        float* gh = Gsh[j & 1];
        if (stager) {
#pragma unroll
            for (int n = 0; n < 9; n++) gh[n * GSH_STRIDE + tid] = gr[n];
        }
        __syncthreads();

        if (stager && j < TT - 1) {
            const float* src = g_hs + (size_t)(j + 1) * BB * HH;
#pragma unroll
            for (int n = 0; n < 9; n++) {
                int iv = idxr[n];
                gr[n] = (iv < BB) ? src[(size_t)iv * HH + tid] : 0.f;
            }
        }

        // ---- scores: chunk-pattern LDS.128 reads, h-pair FMA2, no packs ----
        float pA[9], pB[9];
#pragma unroll
        for (int n = 0; n < 9; n++) {
            const ulonglong2* gp = reinterpret_cast<const ulonglong2*>(
                gh + n * GSH_STRIDE + 4 * hq);
            u64 sA = 0ULL, sB = 0ULL;
#pragma unroll
            for (int c = 0; c < 4; c++) {
                ulonglong2 gv = gp[16 * c];
                FMA_F32X2(sA, gv.x, hspA[2*c],   sA);
                FMA_F32X2(sB, gv.x, hspB[2*c],   sB);
                FMA_F32X2(sA, gv.y, hspA[2*c+1], sA);
                FMA_F32X2(sB, gv.y, hspB[2*c+1], sB);
            }
            float l0, l1;
            UNPACK_F32X2(l0, l1, sA); pA[n] = l0 + l1;
            UNPACK_F32X2(l0, l1, sB); pB[n] = l0 + l1;
        }

        // split-reduce: own set finishes in own bit3-half
        float pw[9];
#pragma unroll
        for (int n = 0; n < 9; n++) {
            float send = isB ? pA[n] : pB[n];
            float keep = isB ? pB[n] : pA[n];
            float v = keep + __shfl_xor_sync(0xffffffffu, send, 8);
            v += __shfl_xor_sync(0xffffffffu, v, 1);
            v += __shfl_xor_sync(0xffffffffu, v, 2);
            v += __shfl_xor_sync(0xffffffffu, v, 4);
            pw[n] = v;
        }

        // softmax on own set only
        {
            float m = pw[0];
#pragma unroll
            for (int n = 1; n < 9; n++) m = fmaxf(m, pw[n]);
            float sum = 0.f;
#pragma unroll
            for (int n = 0; n < 9; n++) { pw[n] = __expf(pw[n] - m); sum += pw[n]; }
            float r = 1.f / sum;
#pragma unroll
            for (int n = 0; n < 9; n++) pw[n] *= r;
        }

        // swap softmaxed sets back
#pragma unroll
        for (int n = 0; n < 9; n++) {
            float other = __shfl_xor_sync(0xffffffffu, pw[n], 8);
            pA[n] = isB ? other : pw[n];
            pB[n] = isB ? pw[n] : other;
        }

        if (hq < 9) {
            out_attn[(((size_t)(iA * TT + j)) * BB + b) * 9 + hq] = pA[hq];
            out_attn[(((size_t)(iB * TT + j)) * BB + b) * 9 + hq] = pB[hq];
        }

        // ---- masked context (j < i), same chunk pattern ----
        if (j < iB) {
            const bool dA = (j < iA);
#pragma unroll
            for (int n = 0; n < 9; n++) {
                float vA = dA ? pA[n] : 0.f;
                u64 pdA, pdB;
                PACK_F32X2(pdA, vA, vA);
                PACK_F32X2(pdB, pB[n], pB[n]);
                const float* rowp = gh + n * GSH_STRIDE + 4 * hq;
#pragma unroll
                for (int c = 0; c < 4; c++) {
                    ulonglong2 gv = *reinterpret_cast<const ulonglong2*>(rowp + 64 * c);
                    FMA_F32X2(acc2[0][c][0], pdA, gv.x, acc2[0][c][0]);
                    FMA_F32X2(acc2[0][c][1], pdA, gv.y, acc2[0][c][1]);
                    FMA_F32X2(acc2[1][c][0], pdB, gv.x, acc2[1][c][0]);
                    FMA_F32X2(acc2[1][c][1], pdB, gv.y, acc2[1][c][1]);
                }
            }
        }
    }

    // ---- head: reuse hsp registers (same chunk layout as sWl indexing) ----
#pragma unroll
    for (int i = 0; i < 2; i++) {
        const int gi = (i == 0) ? iA : iB;
        const u64* hsp = (i == 0) ? hspA : hspB;
        const u64* ac0 = &acc2[i][0][0];
        float t = 0.f;
#pragma unroll
        for (int c = 0; c < 4; c++) {
#pragma unroll
            for (int e2 = 0; e2 < 2; e2++) {
                const int h0 = 4 * hq + 64 * c + 2 * e2;
                float h0v, h1v, a0v, a1v;
                UNPACK_F32X2(h0v, h1v, hsp[2*c + e2]);
                UNPACK_F32X2(a0v, a1v, ac0[2*c + e2]);
                if (gi == 0) { a0v = h0v; a1v = h1v; }
                t += a0v * sWl[h0]     + h0v * sWl[256 + h0];
                t += a1v * sWl[h0 + 1] + h1v * sWl[256 + h0 + 1];
            }
        }
        t += __shfl_xor_sync(0xffffffffu, t, 1);
        t += __shfl_xor_sync(0xffffffffu, t, 2);
        t += __shfl_xor_sync(0xffffffffu, t, 4);
        t += __shfl_xor_sync(0xffffffffu, t, 8);
        if (hq == 0)
            out[(size_t)gi * BB + b] = fmaxf(t + bl, 0.f);
    }
}

// ---------------------------------------------------------------------------
extern "C" void kernel_launch(void* const* d_in, const int* in_sizes, int n_in,
                              void* d_out, int out_size)
{
    const float* data  = (const float*)d_in[0];
    const int*   nidx  = (const int*)d_in[1];
    /* d_in[2] = haven_flag (always 0, branch unused) */
    const float* h0    = (const float*)d_in[3];
    const float* W_ih  = (const float*)d_in[4];
    const float* W_hh  = (const float*)d_in[5];
    const float* b_ih  = (const float*)d_in[6];
    const float* b_hh  = (const float*)d_in[7];
    const float* W_lin = (const float*)d_in[8];
    const float* b_lin = (const float*)d_in[9];
    float* out = (float*)d_out;

    (void)in_sizes; (void)n_in; (void)out_size;

    wt_kernel<<<256, 256>>>(W_hh);
    xw_kernel<<<1024, 256>>>(data, W_ih, b_ih, b_hh);

    const int rnn_smem = (2 * 8 * 260 + 8 * 2048) * (int)sizeof(float);
    cudaFuncSetAttribute(rnn_scan_kernel,
                         cudaFuncAttributeMaxDynamicSharedMemorySize, rnn_smem);
    rnn_scan_kernel<<<128, 512, rnn_smem>>>(h0);

    attn_kernel<<<1024, 512>>>(nidx, W_lin, b_lin, out);
}

// round 17
// speedup vs baseline: 2.2397x; 2.2397x over previous
#include <cuda_runtime.h>

#define TT 64
#define BB 1024
#define II 64
#define HH 256

__device__ float g_hs[(size_t)TT * BB * HH];
__device__ float g_WT[HH * HH];   // WT[k][h] = W_hh[h][k]

typedef unsigned long long u64;

#define FMA_F32X2(d, a, b, c) \
    asm("fma.rn.f32x2 %0, %1, %2, %3;" : "=l"(d) : "l"(a), "l"(b), "l"(c))
#define PACK_F32X2(out, lo, hi) \
    asm("mov.b64 %0, {%1, %2};" : "=l"(out) : "f"(lo), "f"(hi))
#define UNPACK_F32X2(lo, hi, in) \
    asm("mov.b64 {%0, %1}, %2;" : "=f"(lo), "=f"(hi) : "l"(in))

// ---------------------------------------------------------------------------
// Kernel 0: transpose W_hh (one-time, 256 KB)
// ---------------------------------------------------------------------------
__global__ void __launch_bounds__(256) wt_kernel(const float* __restrict__ W_hh)
{
    const int k = blockIdx.x;
    const int h = threadIdx.x;
    g_WT[k * HH + h] = W_hh[h * HH + k];
}

// ---------------------------------------------------------------------------
// Kernel 1: g_hs[t,b,h] = data[t,b,:] . W_ih[h,:] + b_ih[h] + b_hh[h]
// 16-row tiles -> 4 barrier-pairs (validated in R16).
// ---------------------------------------------------------------------------
__global__ void __launch_bounds__(256) xw_kernel(
    const float* __restrict__ data,
    const float* __restrict__ W_ih,
    const float* __restrict__ b_ih,
    const float* __restrict__ b_hh)
{
    __shared__ float sX[1024];   // 16 rows x 64 inputs
    const int tid = threadIdx.x;
    const long r0 = (long)blockIdx.x * 64;

    float w[64];
    const float4* W4 = reinterpret_cast<const float4*>(W_ih) + tid * 16;
#pragma unroll
    for (int c = 0; c < 16; c++) {
        float4 v = W4[c];
        w[4*c+0] = v.x; w[4*c+1] = v.y; w[4*c+2] = v.z; w[4*c+3] = v.w;
    }
    const float bsum = b_ih[tid] + b_hh[tid];
    const float4* D4 = reinterpret_cast<const float4*>(data + r0 * II);

    for (int it = 0; it < 4; it++) {
        __syncthreads();
        reinterpret_cast<float4*>(sX)[tid] = D4[it * 256 + tid];
        __syncthreads();

        const float4* X4 = reinterpret_cast<const float4*>(sX);
#pragma unroll
        for (int r = 0; r < 16; r++) {
            float a = bsum;
#pragma unroll
            for (int c = 0; c < 16; c++) {
                float4 x = X4[r * 16 + c];
                a += x.x*w[4*c] + x.y*w[4*c+1] + x.z*w[4*c+2] + x.w*w[4*c+3];
            }
            g_hs[(r0 + it * 16 + r) * HH + tid] = a;
        }
    }
}

// ---------------------------------------------------------------------------
// Kernel 2: persistent RNN scan, k-split (validated).
// ---------------------------------------------------------------------------
__global__ void __launch_bounds__(512) rnn_scan_kernel(
    const float* __restrict__ h0_in)
{
    extern __shared__ float sm[];
    float* hp   = sm;                 // [2][8][260]
    float* part = sm + 2 * 8 * 260;   // [8][2048]

    const int tid = threadIdx.x;
    const int kq = tid >> 6;
    const int hw = tid & 63;
    const int b0 = blockIdx.x * 8;

    for (int m = tid; m < 2048; m += 512) {
        int bb = m >> 8, k = m & 255;
        hp[bb * 260 + k] = h0_in[(size_t)(b0 + bb) * HH + k];
    }
    __syncthreads();

    const int off = tid * 4;
    const int rb_b = off >> 8;
    const int rb_h = off & 255;

    for (int t = 0; t < TT; t++) {
        const int rb = t & 1;
        const float* hpc = hp + rb * 8 * 260;

        u64 acc[8][2];
#pragma unroll
        for (int bb = 0; bb < 8; bb++) { acc[bb][0] = 0ULL; acc[bb][1] = 0ULL; }

#pragma unroll 2
        for (int k4 = 0; k4 < 8; k4++) {
            const int k = kq * 32 + k4 * 4;
            const ulonglong2* wr =
                reinterpret_cast<const ulonglong2*>(g_WT + (size_t)k * HH) + hw;
            ulonglong2 w0 = wr[0];
            ulonglong2 w1 = wr[64];
            ulonglong2 w2 = wr[128];
            ulonglong2 w3 = wr[192];
#pragma unroll
            for (int bb = 0; bb < 8; bb++) {
                float4 hv = *reinterpret_cast<const float4*>(hpc + bb * 260 + k);
                u64 hd;
                PACK_F32X2(hd, hv.x, hv.x);
                FMA_F32X2(acc[bb][0], w0.x, hd, acc[bb][0]);
                FMA_F32X2(acc[bb][1], w0.y, hd, acc[bb][1]);
                PACK_F32X2(hd, hv.y, hv.y);
                FMA_F32X2(acc[bb][0], w1.x, hd, acc[bb][0]);
                FMA_F32X2(acc[bb][1], w1.y, hd, acc[bb][1]);
                PACK_F32X2(hd, hv.z, hv.z);
                FMA_F32X2(acc[bb][0], w2.x, hd, acc[bb][0]);
                FMA_F32X2(acc[bb][1], w2.y, hd, acc[bb][1]);
                PACK_F32X2(hd, hv.w, hv.w);
                FMA_F32X2(acc[bb][0], w3.x, hd, acc[bb][0]);
                FMA_F32X2(acc[bb][1], w3.y, hd, acc[bb][1]);
            }
        }

#pragma unroll
        for (int bb = 0; bb < 8; bb++) {
            float f0, f1, f2, f3;
            UNPACK_F32X2(f0, f1, acc[bb][0]);
            UNPACK_F32X2(f2, f3, acc[bb][1]);
            *reinterpret_cast<float4*>(part + kq * 2048 + bb * 256 + hw * 4) =
                make_float4(f0, f1, f2, f3);
        }
        __syncthreads();

        {
            float* hs_t = g_hs + (size_t)t * BB * HH;
            float4 r = *reinterpret_cast<const float4*>(
                hs_t + (size_t)(b0 + rb_b) * HH + rb_h);
#pragma unroll
            for (int q = 0; q < 8; q++) {
                float4 pv = *reinterpret_cast<const float4*>(part + q * 2048 + off);
                r.x += pv.x; r.y += pv.y; r.z += pv.z; r.w += pv.w;
            }
            r.x = fmaxf(r.x, 0.f); r.y = fmaxf(r.y, 0.f);
            r.z = fmaxf(r.z, 0.f); r.w = fmaxf(r.w, 0.f);
            *reinterpret_cast<float4*>(
                hs_t + (size_t)(b0 + rb_b) * HH + rb_h) = r;
            *reinterpret_cast<float4*>(
                hp + (rb ^ 1) * 8 * 260 + rb_b * 260 + rb_h) = r;
        }
        __syncthreads();
    }
}

// ---------------------------------------------------------------------------
// Kernel 3: attention — R15 base (dual Gsn/Gsh, validated 1610us) with:
//  (a) i-interleave: ip = ((iq&1)<<4)|(iq>>1) -> each warp owns one low-half
//      and one high-half i-pair -> triangular context work balanced per j.
//  (b) Gsn stores vectorized: 4 STS.64 + 1 STS.32 (was 9 STS.32, 2-way conf).
// Everything else byte-identical to R15.
// ---------------------------------------------------------------------------
#define GSN_STRIDE 10
#define GSN_SZ     2560
#define GSH_STRIDE 264

__global__ void __launch_bounds__(512, 1) attn_kernel(
    const int* __restrict__ nine_idx,
    const float* __restrict__ W_lin,
    const float* __restrict__ b_lin,
    float* __restrict__ out)
{
    __shared__ float Gsn[2][GSN_SZ];
    __shared__ float Gsh[2][9 * GSH_STRIDE];
    __shared__ float sWl[512];
    __shared__ int   sidx[9];

    const int tid   = threadIdx.x;
    const int b     = blockIdx.x;
    const int iq    = tid >> 4;          // 0..31
    const int hq    = tid & 15;          // 0..15
    const int ip    = ((iq & 1) << 4) | (iq >> 1);   // interleaved pair index
    const int iA    = 2 * ip;
    const int iB    = iA + 1;
    const bool isB  = (tid & 8) != 0;    // bit3 of the 16-lane reduce group
    const bool stager = (tid < 256);

    if (tid < 9) sidx[tid] = nine_idx[b * 9 + tid];
    sWl[tid] = W_lin[tid];
    __syncthreads();

    int idxr[9];
#pragma unroll
    for (int n = 0; n < 9; n++) idxr[n] = sidx[n];

    float hsA[16], hsB[16];
    {
        const float* HA = g_hs + ((size_t)iA * BB + b) * HH + hq;
        const float* HB = g_hs + ((size_t)iB * BB + b) * HH + hq;
#pragma unroll
        for (int e = 0; e < 16; e++) { hsA[e] = HA[16 * e]; hsB[e] = HB[16 * e]; }
    }

    u64 acc2[2][4][2];
#pragma unroll
    for (int i = 0; i < 2; i++)
#pragma unroll
        for (int c = 0; c < 4; c++) { acc2[i][c][0] = 0ULL; acc2[i][c][1] = 0ULL; }

    const float bl = b_lin[0];

    float gr[9];
    if (stager) {
#pragma unroll
        for (int n = 0; n < 9; n++) {
            int iv = idxr[n];
            gr[n] = (iv < BB) ? g_hs[(size_t)iv * HH + tid] : 0.f;
        }
    }

    const int gn_st = tid * GSN_STRIDE;

    float* out_attn = out + (size_t)TT * BB;

    for (int j = 0; j < TT; j++) {
        float* gn = Gsn[j & 1];
        float* gh = Gsh[j & 1];
        if (stager) {
            // vectorized Gsn row store: 4 STS.64 + 1 STS.32
            u64 q0, q1, q2, q3;
            PACK_F32X2(q0, gr[0], gr[1]);
            PACK_F32X2(q1, gr[2], gr[3]);
            PACK_F32X2(q2, gr[4], gr[5]);
            PACK_F32X2(q3, gr[6], gr[7]);
            u64* gnp = reinterpret_cast<u64*>(gn + gn_st);
            gnp[0] = q0; gnp[1] = q1; gnp[2] = q2; gnp[3] = q3;
            gn[gn_st + 8] = gr[8];
#pragma unroll
            for (int n = 0; n < 9; n++) gh[n * GSH_STRIDE + tid] = gr[n];
        }
        __syncthreads();

        if (stager && j < TT - 1) {
            const float* src = g_hs + (size_t)(j + 1) * BB * HH;
#pragma unroll
            for (int n = 0; n < 9; n++) {
                int iv = idxr[n];
                gr[n] = (iv < BB) ? src[(size_t)iv * HH + tid] : 0.f;
            }
        }

        u64 s2A[4], s2B[4];
        float s8A = 0.f, s8B = 0.f;
#pragma unroll
        for (int p = 0; p < 4; p++) { s2A[p] = 0ULL; s2B[p] = 0ULL; }

#pragma unroll
        for (int e = 0; e < 16; e++) {
            const float* base = gn + (hq + 16 * e) * GSN_STRIDE;
            u64 g01 = *reinterpret_cast<const u64*>(base);
            u64 g23 = *reinterpret_cast<const u64*>(base + 2);
            u64 g45 = *reinterpret_cast<const u64*>(base + 4);
            u64 g67 = *reinterpret_cast<const u64*>(base + 6);
            float g8v = base[8];
            float xA = hsA[e], xB = hsB[e];
            u64 xdA, xdB;
            PACK_F32X2(xdA, xA, xA);
            PACK_F32X2(xdB, xB, xB);
            FMA_F32X2(s2A[0], g01, xdA, s2A[0]);
            FMA_F32X2(s2A[1], g23, xdA, s2A[1]);
            FMA_F32X2(s2A[2], g45, xdA, s2A[2]);
            FMA_F32X2(s2A[3], g67, xdA, s2A[3]);
            FMA_F32X2(s2B[0], g01, xdB, s2B[0]);
            FMA_F32X2(s2B[1], g23, xdB, s2B[1]);
            FMA_F32X2(s2B[2], g45, xdB, s2B[2]);
            FMA_F32X2(s2B[3], g67, xdB, s2B[3]);
            s8A += xA * g8v;
            s8B += xB * g8v;
        }

        float pA[9], pB[9];
#pragma unroll
        for (int p = 0; p < 4; p++) {
            UNPACK_F32X2(pA[2*p], pA[2*p+1], s2A[p]);
            UNPACK_F32X2(pB[2*p], pB[2*p+1], s2B[p]);
        }
        pA[8] = s8A; pB[8] = s8B;

        // split-reduce: own set finishes in own bit3-half
        float pw[9];
#pragma unroll
        for (int n = 0; n < 9; n++) {
            float send = isB ? pA[n] : pB[n];
            float keep = isB ? pB[n] : pA[n];
            float v = keep + __shfl_xor_sync(0xffffffffu, send, 8);
            v += __shfl_xor_sync(0xffffffffu, v, 1);
            v += __shfl_xor_sync(0xffffffffu, v, 2);
            v += __shfl_xor_sync(0xffffffffu, v, 4);
            pw[n] = v;
        }

        // softmax on own set only
        {
            float m = pw[0];
#pragma unroll
            for (int n = 1; n < 9; n++) m = fmaxf(m, pw[n]);
            float sum = 0.f;
#pragma unroll
            for (int n = 0; n < 9; n++) { pw[n] = __expf(pw[n] - m); sum += pw[n]; }
            float r = 1.f / sum;
#pragma unroll
            for (int n = 0; n < 9; n++) pw[n] *= r;
        }

        // swap softmaxed sets back
#pragma unroll
        for (int n = 0; n < 9; n++) {
            float other = __shfl_xor_sync(0xffffffffu, pw[n], 8);
            pA[n] = isB ? other : pw[n];
            pB[n] = isB ? pw[n] : other;
        }

        if (hq < 9) {
            out_attn[(((size_t)(iA * TT + j)) * BB + b) * 9 + hq] = pA[hq];
            out_attn[(((size_t)(iB * TT + j)) * BB + b) * 9 + hq] = pB[hq];
        }

        if (j < iB) {
            const bool dA = (j < iA);
#pragma unroll
            for (int n = 0; n < 9; n++) {
                float vA = dA ? pA[n] : 0.f;
                u64 pdA, pdB;
                PACK_F32X2(pdA, vA, vA);
                PACK_F32X2(pdB, pB[n], pB[n]);
                const float* rowp = gh + n * GSH_STRIDE + 4 * hq;
#pragma unroll
                for (int c = 0; c < 4; c++) {
                    ulonglong2 gv = *reinterpret_cast<const ulonglong2*>(rowp + 64 * c);
                    FMA_F32X2(acc2[0][c][0], pdA, gv.x, acc2[0][c][0]);
                    FMA_F32X2(acc2[0][c][1], pdA, gv.y, acc2[0][c][1]);
                    FMA_F32X2(acc2[1][c][0], pdB, gv.x, acc2[1][c][0]);
                    FMA_F32X2(acc2[1][c][1], pdB, gv.y, acc2[1][c][1]);
                }
            }
        }
    }

#pragma unroll
    for (int i = 0; i < 2; i++) {
        const int gi = (i == 0) ? iA : iB;
        const float* hrow = g_hs + ((size_t)gi * BB + b) * HH;
        float t = 0.f;
#pragma unroll
        for (int c = 0; c < 4; c++) {
            const int h0 = 4 * hq + 64 * c;
            float4 hv = *reinterpret_cast<const float4*>(hrow + h0);
            float a0, a1, a2, a3;
            UNPACK_F32X2(a0, a1, acc2[i][c][0]);
            UNPACK_F32X2(a2, a3, acc2[i][c][1]);
            if (gi == 0) { a0 = hv.x; a1 = hv.y; a2 = hv.z; a3 = hv.w; }
            t += a0 * sWl[h0]   + hv.x * sWl[256 + h0];
            t += a1 * sWl[h0+1] + hv.y * sWl[256 + h0 + 1];
            t += a2 * sWl[h0+2] + hv.z * sWl[256 + h0 + 2];
            t += a3 * sWl[h0+3] + hv.w * sWl[256 + h0 + 3];
        }
        t += __shfl_xor_sync(0xffffffffu, t, 1);
        t += __shfl_xor_sync(0xffffffffu, t, 2);
        t += __shfl_xor_sync(0xffffffffu, t, 4);
        t += __shfl_xor_sync(0xffffffffu, t, 8);
        if (hq == 0)
            out[(size_t)gi * BB + b] = fmaxf(t + bl, 0.f);
    }
}

// ---------------------------------------------------------------------------
extern "C" void kernel_launch(void* const* d_in, const int* in_sizes, int n_in,
                              void* d_out, int out_size)
{
    const float* data  = (const float*)d_in[0];
    const int*   nidx  = (const int*)d_in[1];
    /* d_in[2] = haven_flag (always 0, branch unused) */
    const float* h0    = (const float*)d_in[3];
    const float* W_ih  = (const float*)d_in[4];
    const float* W_hh  = (const float*)d_in[5];
    const float* b_ih  = (const float*)d_in[6];
    const float* b_hh  = (const float*)d_in[7];
    const float* W_lin = (const float*)d_in[8];
    const float* b_lin = (const float*)d_in[9];
    float* out = (float*)d_out;

    (void)in_sizes; (void)n_in; (void)out_size;

    wt_kernel<<<256, 256>>>(W_hh);
    xw_kernel<<<1024, 256>>>(data, W_ih, b_ih, b_hh);

    const int rnn_smem = (2 * 8 * 260 + 8 * 2048) * (int)sizeof(float);
    cudaFuncSetAttribute(rnn_scan_kernel,
                         cudaFuncAttributeMaxDynamicSharedMemorySize, rnn_smem);
    rnn_scan_kernel<<<128, 512, rnn_smem>>>(h0);

    attn_kernel<<<1024, 512>>>(nidx, W_lin, b_lin, out);
}